// round 11
// baseline (speedup 1.0000x reference)
#include <cuda_runtime.h>
#include <math.h>

#define NN      131072
#define DEG     16
#define NNZE    (NN*DEG)
#define GRID_P  296              // 2 CTAs/SM x 148 SMs co-resident (spin barrier safe)

typedef unsigned long long ull;

// ---- packed f32x2 helpers (Blackwell FFMA2; bit-identical fp32 math) ----
__device__ __forceinline__ ull ffma2(ull a, ull b, ull c) {
    ull d; asm("fma.rn.f32x2 %0, %1, %2, %3;" : "=l"(d) : "l"(a), "l"(b), "l"(c)); return d;
}
__device__ __forceinline__ ull fmul2(ull a, ull b) {
    ull d; asm("mul.rn.f32x2 %0, %1, %2;" : "=l"(d) : "l"(a), "l"(b)); return d;
}
__device__ __forceinline__ ull pack2(float x) {
    ull r; asm("mov.b64 %0, {%1, %1};" : "=l"(r) : "f"(x)); return r;
}
__device__ __forceinline__ float2 unpack2(ull a) {
    float lo, hi; asm("mov.b64 {%0, %1}, %2;" : "=f"(lo), "=f"(hi) : "l"(a));
    return make_float2(lo, hi);
}

// ---------------- scratch (static device globals; no allocation) ----------------
__device__ float  g_y [NN*32];
__device__ float  g_h1[NN*32];
__device__ float  g_h2[NN*64];
__device__ int    g_cnt[NN];
__device__ int    g_rowptr[NN+1];
__device__ int    g_cursor[NN];
__device__ int    g_psum[512];
__device__ float2 g_packed[NNZE];
__device__ unsigned g_barc[8];   // zero-init; generation barriers (self-resetting)
__device__ unsigned g_barg[8];

// ---- grid-wide barrier (all CTAs co-resident by construction) ----
__device__ __forceinline__ void gbar(int i, int grid) {
    __threadfence();
    __syncthreads();
    if (threadIdx.x == 0) {
        unsigned gen = *(volatile unsigned*)&g_barg[i];
        unsigned prev = atomicAdd(&g_barc[i], 1);
        if (prev == (unsigned)grid - 1) {
            g_barc[i] = 0;
            __threadfence();
            atomicAdd(&g_barg[i], 1);
        } else {
            while (*(volatile unsigned*)&g_barg[i] == gen) { }
        }
    }
    __syncthreads();
}

// ---------------- ONE persistent CSR kernel: zero | hist | 3-stage scan | scatter
__global__ void __launch_bounds__(256, 2) k_csr(
    const int* __restrict__ rows, const int* __restrict__ cols,
    const float* __restrict__ vals)
{
    __shared__ int ss[256];
    int t = threadIdx.x;
    int gtid = blockIdx.x*256 + t;
    const int gstride = GRID_P*256;

    // phase 0: zero counts
    for (int i = gtid; i < NN; i += gstride) g_cnt[i] = 0;
    gbar(0, GRID_P);

    // phase 1: histogram
    #pragma unroll 4
    for (int e = gtid; e < NNZE; e += gstride) atomicAdd(&g_cnt[rows[e]], 1);
    gbar(1, GRID_P);

    // phase 2a: 512 virtual-block sums -> g_psum
    for (int b = blockIdx.x; b < 512; b += GRID_P) {
        ss[t] = __ldcg(&g_cnt[b*256 + t]);
        __syncthreads();
        for (int off = 128; off > 0; off >>= 1) {
            if (t < off) ss[t] += ss[t+off];
            __syncthreads();
        }
        if (t == 0) g_psum[b] = ss[0];
        __syncthreads();
    }
    gbar(2, GRID_P);

    // phase 2b: CTA0 scans the 512 block sums (inclusive)
    if (blockIdx.x == 0) {
        int a  = __ldcg(&g_psum[2*t]);
        int bb = __ldcg(&g_psum[2*t+1]);
        int pair = a + bb;
        ss[t] = pair;
        __syncthreads();
        for (int off = 1; off < 256; off <<= 1) {
            int v = (t >= off) ? ss[t-off] : 0;
            __syncthreads();
            ss[t] += v;
            __syncthreads();
        }
        int excl = ss[t] - pair;
        g_psum[2*t]   = excl + a;
        g_psum[2*t+1] = excl + pair;
    }
    gbar(3, GRID_P);

    // phase 2c: per-block exclusive scan + base -> rowptr/cursor
    for (int b = blockIdx.x; b < 512; b += GRID_P) {
        int c = __ldcg(&g_cnt[b*256 + t]);
        ss[t] = c;
        __syncthreads();
        for (int off = 1; off < 256; off <<= 1) {
            int v = (t >= off) ? ss[t-off] : 0;
            __syncthreads();
            ss[t] += v;
            __syncthreads();
        }
        int base = (b == 0) ? 0 : __ldcg(&g_psum[b-1]);
        int excl = base + ss[t] - c;
        g_rowptr[b*256 + t] = excl;
        g_cursor[b*256 + t] = excl;
        __syncthreads();
    }
    if (blockIdx.x == 0 && t == 0) g_rowptr[NN] = __ldcg(&g_psum[511]);
    gbar(4, GRID_P);

    // phase 3: scatter edges into row-grouped layout
    #pragma unroll 4
    for (int e = gtid; e < NNZE; e += gstride) {
        int r = rows[e];
        int pos = atomicAdd(&g_cursor[r], 1);
        g_packed[pos] = make_float2(__int_as_float(cols[e]), vals[e]);
    }
}

// ---------------- y = x @ W1  (project 128->32 BEFORE SpMM; packed FMA) ----------
__global__ void __launch_bounds__(256) k_xw1(const float* __restrict__ x,
                                             const float* __restrict__ W1) {
    __shared__ float sW[128*32];
    int t = threadIdx.x;
    for (int i = t; i < 1024; i += 256) ((float4*)sW)[i] = ((const float4*)W1)[i];
    __syncthreads();
    int row = blockIdx.x*256 + t;
    const float4* xr = (const float4*)(x + (size_t)row*128);
    ull acc[16];
    #pragma unroll
    for (int j = 0; j < 16; j++) acc[j] = 0ull;
    #pragma unroll 4
    for (int k4 = 0; k4 < 32; k4++) {
        float4 xv = xr[k4];
        #pragma unroll
        for (int c = 0; c < 4; c++) {
            float xk = (c==0) ? xv.x : (c==1) ? xv.y : (c==2) ? xv.z : xv.w;
            ull xp = pack2(xk);
            const ulonglong2* wr = (const ulonglong2*)(sW + (k4*4+c)*32);
            #pragma unroll
            for (int j = 0; j < 8; j++) {
                ulonglong2 w = wr[j];
                acc[2*j+0] = ffma2(xp, w.x, acc[2*j+0]);
                acc[2*j+1] = ffma2(xp, w.y, acc[2*j+1]);
            }
        }
    }
    ulonglong2* yo = (ulonglong2*)(g_y + (size_t)row*32);
    #pragma unroll
    for (int j = 0; j < 8; j++) {
        ulonglong2 u; u.x = acc[2*j]; u.y = acc[2*j+1];
        yo[j] = u;
    }
}

// ------- persistent SpMM1 + SpMM2@W2 (W2 staged ONCE per CTA; 4-way gather MLP) --
__global__ void __launch_bounds__(256, 2) k_spmm12(
    const float* __restrict__ b1,
    const float* __restrict__ W2, const float* __restrict__ b2)
{
    __shared__ float sW[32*64];
    __shared__ float sz[8][33];
    int t = threadIdx.x;
    int lane = t & 31, wl = t >> 5;
    int gw = (blockIdx.x*256 + t) >> 5;
    const int nwarp = GRID_P*8;

    for (int i = t; i < 512; i += 256) ((float4*)sW)[i] = ((const float4*)W2)[i];
    __syncthreads();

    // ---- SpMM1: h1 = relu(spmm(y) + b1) ----
    float bb1 = b1[lane];
    for (int w = gw; w < NN; w += nwarp) {
        int s = g_rowptr[w], e = g_rowptr[w+1];
        float a0 = 0.f, a1 = 0.f, a2 = 0.f, a3 = 0.f;
        int i = s;
        for (; i + 3 < e; i += 4) {
            float2 pa = g_packed[i],   pb = g_packed[i+1];
            float2 pc = g_packed[i+2], pd = g_packed[i+3];
            a0 += pa.y * g_y[__float_as_int(pa.x)*32 + lane];
            a1 += pb.y * g_y[__float_as_int(pb.x)*32 + lane];
            a2 += pc.y * g_y[__float_as_int(pc.x)*32 + lane];
            a3 += pd.y * g_y[__float_as_int(pd.x)*32 + lane];
        }
        for (; i < e; i++) {
            float2 pa = g_packed[i];
            a0 += pa.y * g_y[__float_as_int(pa.x)*32 + lane];
        }
        g_h1[w*32 + lane] = fmaxf((a0+a1) + (a2+a3) + bb1, 0.f);
    }
    gbar(5, GRID_P);

    // ---- SpMM2 fused with @W2: h2 = relu(spmm(h1)@W2 + b2) ----
    float b2a = b2[lane], b2b = b2[lane+32];
    for (int w = gw; w < NN; w += nwarp) {
        int s = g_rowptr[w], e = g_rowptr[w+1];
        float a0 = 0.f, a1 = 0.f, a2 = 0.f, a3 = 0.f;
        int i = s;
        for (; i + 3 < e; i += 4) {
            float2 pa = g_packed[i],   pb = g_packed[i+1];
            float2 pc = g_packed[i+2], pd = g_packed[i+3];
            a0 += pa.y * __ldcg(&g_h1[__float_as_int(pa.x)*32 + lane]);
            a1 += pb.y * __ldcg(&g_h1[__float_as_int(pb.x)*32 + lane]);
            a2 += pc.y * __ldcg(&g_h1[__float_as_int(pc.x)*32 + lane]);
            a3 += pd.y * __ldcg(&g_h1[__float_as_int(pd.x)*32 + lane]);
        }
        for (; i < e; i++) {
            float2 pa = g_packed[i];
            a0 += pa.y * __ldcg(&g_h1[__float_as_int(pa.x)*32 + lane]);
        }
        sz[wl][lane] = (a0+a1) + (a2+a3);
        __syncwarp();
        float o0 = b2a, o1 = b2b;
        #pragma unroll
        for (int k = 0; k < 32; k++) {
            float zv = sz[wl][k];
            o0 += zv * sW[k*64 + lane];
            o1 += zv * sW[k*64 + lane + 32];
        }
        size_t off = (size_t)w * 64;
        g_h2[off + lane]      = fmaxf(o0, 0.f);
        g_h2[off + lane + 32] = fmaxf(o1, 0.f);
        __syncwarp();
    }
}

// ---------------- transformer: head-split attention (broadcast K/V loads) --------
// smem: scr (17408 fl; Wqkv -> Q/O rows -> Wf1|Wf2|Wc)
//       sK (256x68), sV (256x68); sK reused for Wo, then (with sV) FFN hidden rows
#define SCR_FLOATS  17408
#define QO_STRIDE   66
#define KV_STRIDE   68
#define SH_STRIDE   133
#define SMEM_FLOATS (SCR_FLOATS + 2*256*KV_STRIDE)
#define SMEM_BYTES  (SMEM_FLOATS*4)

__device__ __forceinline__ void gemm64p(const float* xin,
                                        const float* __restrict__ sw, int ws,
                                        int coff, ull (&acc)[16]) {
    #pragma unroll
    for (int k = 0; k < 64; k++) {
        ull xp = pack2(xin[k]);
        const ulonglong2* wr = (const ulonglong2*)(sw + k*ws + coff);
        #pragma unroll
        for (int j = 0; j < 8; j++) {
            ulonglong2 w = wr[j];
            acc[2*j+0] = ffma2(xp, w.x, acc[2*j+0]);
            acc[2*j+1] = ffma2(xp, w.y, acc[2*j+1]);
        }
    }
}

__device__ __forceinline__ void layernorm64(float (&v)[64], const float* __restrict__ g,
                                            const float* __restrict__ b) {
    float mu = 0.f;
    #pragma unroll
    for (int j = 0; j < 64; j++) mu += v[j];
    mu *= (1.f/64.f);
    float var = 0.f;
    #pragma unroll
    for (int j = 0; j < 64; j++) { float d = v[j]-mu; var += d*d; }
    var *= (1.f/64.f);
    float inv = rsqrtf(var + 1e-5f);
    #pragma unroll
    for (int j = 0; j < 64; j++) v[j] = (v[j]-mu)*inv*g[j] + b[j];
}

__global__ void __launch_bounds__(256) k_tr(
    const float* __restrict__ Wqkv, const float* __restrict__ bqkv,
    const float* __restrict__ Wo,   const float* __restrict__ bo,
    const float* __restrict__ g1,   const float* __restrict__ be1,
    const float* __restrict__ Wf1,  const float* __restrict__ bf1,
    const float* __restrict__ Wf2,  const float* __restrict__ bf2,
    const float* __restrict__ g2,   const float* __restrict__ be2,
    const float* __restrict__ Wc,   const float* __restrict__ bc,
    float* __restrict__ out)
{
    extern __shared__ float sm[];
    float* scr = sm;                           // 17408 floats
    float* sK  = sm + SCR_FLOATS;              // 256 x 68
    float* sV  = sK + 256*KV_STRIDE;           // 256 x 68
    float* sH  = sK;                           // FFN hidden rows 256 x 133 (K/V dead)
    int t = threadIdx.x;
    int blk = blockIdx.x;
    const float4* xr4 = (const float4*)(g_h2 + ((size_t)blk*256 + t)*64);

    // ---- B1: stage W_qkv (64x192 = 12288 floats) into scr ----
    for (int i = t; i < 3072; i += 256) ((float4*)scr)[i] = ((const float4*)Wqkv)[i];
    __syncthreads();

    // ---- qkv projection (thread = token); q2 regs, K/V -> smem ----
    ull q2[32];
    #pragma unroll
    for (int ch = 0; ch < 6; ch++) {
        ull acc[16];
        const ull* bp = (const ull*)(bqkv + ch*32);
        #pragma unroll
        for (int j = 0; j < 16; j++) acc[j] = bp[j];
        #pragma unroll
        for (int k4 = 0; k4 < 16; k4++) {
            float4 xv = xr4[k4];
            #pragma unroll
            for (int c = 0; c < 4; c++) {
                float xk = (c==0) ? xv.x : (c==1) ? xv.y : (c==2) ? xv.z : xv.w;
                ull xp = pack2(xk);
                const ulonglong2* wr = (const ulonglong2*)(scr + (k4*4+c)*192 + ch*32);
                #pragma unroll
                for (int j = 0; j < 8; j++) {
                    ulonglong2 w = wr[j];
                    acc[2*j+0] = ffma2(xp, w.x, acc[2*j+0]);
                    acc[2*j+1] = ffma2(xp, w.y, acc[2*j+1]);
                }
            }
        }
        if (ch < 2) {
            #pragma unroll
            for (int j = 0; j < 16; j++) q2[ch*16 + j] = acc[j];
        } else {
            float* dst = ((ch < 4) ? sK : sV) + t*KV_STRIDE + (ch & 1)*32;
            #pragma unroll
            for (int j = 0; j < 8; j++) {
                ulonglong2 u; u.x = acc[2*j]; u.y = acc[2*j+1];
                ((ulonglong2*)dst)[j] = u;
            }
        }
    }
    __syncthreads();   // B2: everyone done reading Wqkv; K/V complete

    // ---- park q rows in scr (overwrites Wqkv) ----
    #pragma unroll
    for (int j = 0; j < 32; j++)
        *(ull*)&scr[t*QO_STRIDE + 2*j] = q2[j];
    __syncthreads();   // B2b: Q visible

    // ---- attention: thread = (head h, 4 tokens); K/V loads broadcast per warp ----
    {
        int h  = t >> 6;          // 0..3
        int tb = t & 63;          // token base
        ull q[32];                // q[m*8+j] : token m, dim pair j (within head)
        #pragma unroll
        for (int m = 0; m < 4; m++) {
            int tok = tb + 64*m;
            #pragma unroll
            for (int j = 0; j < 8; j++)
                q[m*8+j] = *(const ull*)&scr[tok*QO_STRIDE + h*16 + 2*j];
        }

        // pass 1: per-token max
        float mx[4];
        #pragma unroll
        for (int m = 0; m < 4; m++) mx[m] = -1e30f;
        for (int kk = 0; kk < 256; kk++) {
            const ulonglong2* kp = (const ulonglong2*)(sK + kk*KV_STRIDE + h*16);
            ulonglong2 kA = kp[0], kB = kp[1], kC = kp[2], kD = kp[3];
            #pragma unroll
            for (int m = 0; m < 4; m++) {
                ull sa = fmul2(q[m*8+0], kA.x);
                ull sb = fmul2(q[m*8+1], kA.y);
                sa = ffma2(q[m*8+2], kB.x, sa);
                sb = ffma2(q[m*8+3], kB.y, sb);
                sa = ffma2(q[m*8+4], kC.x, sa);
                sb = ffma2(q[m*8+5], kC.y, sb);
                sa = ffma2(q[m*8+6], kD.x, sa);
                sb = ffma2(q[m*8+7], kD.y, sb);
                float2 u = unpack2(sa), v = unpack2(sb);
                mx[m] = fmaxf(mx[m], (u.x + u.y) + (v.x + v.y));
            }
        }

        // pass 2: softmax + ctx
        float l[4];
        ull c[32];
        #pragma unroll
        for (int m = 0; m < 4; m++) l[m] = 0.f;
        #pragma unroll
        for (int j = 0; j < 32; j++) c[j] = 0ull;
        for (int kk = 0; kk < 256; kk++) {
            const ulonglong2* kp = (const ulonglong2*)(sK + kk*KV_STRIDE + h*16);
            ulonglong2 kA = kp[0], kB = kp[1], kC = kp[2], kD = kp[3];
            const ulonglong2* vp = (const ulonglong2*)(sV + kk*KV_STRIDE + h*16);
            ulonglong2 vA = vp[0], vB = vp[1], vC = vp[2], vD = vp[3];
            #pragma unroll
            for (int m = 0; m < 4; m++) {
                ull sa = fmul2(q[m*8+0], kA.x);
                ull sb = fmul2(q[m*8+1], kA.y);
                sa = ffma2(q[m*8+2], kB.x, sa);
                sb = ffma2(q[m*8+3], kB.y, sb);
                sa = ffma2(q[m*8+4], kC.x, sa);
                sb = ffma2(q[m*8+5], kC.y, sb);
                sa = ffma2(q[m*8+6], kD.x, sa);
                sb = ffma2(q[m*8+7], kD.y, sb);
                float2 u = unpack2(sa), v = unpack2(sb);
                float p = __expf((((u.x+u.y)+(v.x+v.y)) - mx[m]) * 0.25f);
                l[m] += p;
                ull pp = pack2(p);
                c[m*8+0] = ffma2(pp, vA.x, c[m*8+0]);
                c[m*8+1] = ffma2(pp, vA.y, c[m*8+1]);
                c[m*8+2] = ffma2(pp, vB.x, c[m*8+2]);
                c[m*8+3] = ffma2(pp, vB.y, c[m*8+3]);
                c[m*8+4] = ffma2(pp, vC.x, c[m*8+4]);
                c[m*8+5] = ffma2(pp, vC.y, c[m*8+5]);
                c[m*8+6] = ffma2(pp, vD.x, c[m*8+6]);
                c[m*8+7] = ffma2(pp, vD.y, c[m*8+7]);
            }
        }

        // normalize + write o to scr (same cells this thread read q from: no race)
        #pragma unroll
        for (int m = 0; m < 4; m++) {
            int tok = tb + 64*m;
            ull inv = pack2(1.f / l[m]);
            #pragma unroll
            for (int j = 0; j < 8; j++)
                *(ull*)&scr[tok*QO_STRIDE + h*16 + 2*j] = fmul2(c[m*8+j], inv);
        }
    }
    __syncthreads();   // B3: attention done, O complete, K/V dead

    // stage W_o (64x64 = 4096 floats) into sK
    for (int i = t; i < 1024; i += 256) ((float4*)sK)[i] = ((const float4*)Wo)[i];
    __syncthreads();   // B4

    // ---- a = o @ W_o + b_o;  x1 = LN1(x + a)  (thread = token) ----
    float o[64];
    #pragma unroll
    for (int j = 0; j < 32; j++) {
        float2 v = unpack2(*(const ull*)&scr[t*QO_STRIDE + 2*j]);
        o[2*j] = v.x; o[2*j+1] = v.y;
    }
    float x1[64];
    #pragma unroll
    for (int ch = 0; ch < 2; ch++) {
        ull acc[16];
        const ull* bp = (const ull*)(bo + ch*32);
        #pragma unroll
        for (int j = 0; j < 16; j++) acc[j] = bp[j];
        gemm64p(o, sK, 64, ch*32, acc);
        #pragma unroll
        for (int j = 0; j < 16; j++) {
            float2 v = unpack2(acc[j]);
            x1[ch*32 + 2*j + 0] = v.x;
            x1[ch*32 + 2*j + 1] = v.y;
        }
    }
    #pragma unroll
    for (int k4 = 0; k4 < 16; k4++) {
        float4 xv = xr4[k4];
        x1[4*k4+0] += xv.x; x1[4*k4+1] += xv.y; x1[4*k4+2] += xv.z; x1[4*k4+3] += xv.w;
    }
    layernorm64(x1, g1, be1);
    __syncthreads();   // B5: O and W_o dead

    // stage Wf1 (8192), Wf2 (8192), Wc (1024) into scr
    for (int i = t; i < 2048; i += 256) ((float4*)scr)[i] = ((const float4*)Wf1)[i];
    for (int i = t; i < 2048; i += 256) ((float4*)(scr + 8192))[i] = ((const float4*)Wf2)[i];
    for (int i = t; i < 256;  i += 256) ((float4*)(scr + 16384))[i] = ((const float4*)Wc)[i];
    __syncthreads();   // B5b

    // ---- FFN up: h = gelu(x1 @ W_ff1 + b_ff1) -> own smem row (no sync needed) --
    float* hrow = sH + t*SH_STRIDE;
    #pragma unroll
    for (int ch = 0; ch < 4; ch++) {
        ull acc[16];
        const ull* bp = (const ull*)(bf1 + ch*32);
        #pragma unroll
        for (int j = 0; j < 16; j++) acc[j] = bp[j];
        gemm64p(x1, scr, 128, ch*32, acc);
        #pragma unroll
        for (int j = 0; j < 16; j++) {
            float2 v = unpack2(acc[j]);
            hrow[ch*32 + 2*j + 0] = 0.5f*v.x*(1.f + erff(v.x*0.70710678118654752f));
            hrow[ch*32 + 2*j + 1] = 0.5f*v.y*(1.f + erff(v.y*0.70710678118654752f));
        }
    }

    // ---- FFN down + residual + LN2 ----
    float x2[64];
    #pragma unroll
    for (int ch = 0; ch < 2; ch++) {
        ull acc[16];
        const ull* bp = (const ull*)(bf2 + ch*32);
        #pragma unroll
        for (int j = 0; j < 16; j++) acc[j] = bp[j];
        #pragma unroll 4
        for (int k = 0; k < 128; k++) {
            ull hp = pack2(hrow[k]);
            const ulonglong2* wr = (const ulonglong2*)(scr + 8192 + k*64 + ch*32);
            #pragma unroll
            for (int j = 0; j < 8; j++) {
                ulonglong2 w = wr[j];
                acc[2*j+0] = ffma2(hp, w.x, acc[2*j+0]);
                acc[2*j+1] = ffma2(hp, w.y, acc[2*j+1]);
            }
        }
        #pragma unroll
        for (int j = 0; j < 16; j++) {
            float2 v = unpack2(acc[j]);
            x2[ch*32 + 2*j + 0] = v.x + x1[ch*32 + 2*j + 0];
            x2[ch*32 + 2*j + 1] = v.y + x1[ch*32 + 2*j + 1];
        }
    }
    layernorm64(x2, g2, be2);

    // ---- classifier + log_softmax ----
    ull lg2[8];
    const ull* bcp = (const ull*)bc;
    #pragma unroll
    for (int j = 0; j < 8; j++) lg2[j] = bcp[j];
    #pragma unroll
    for (int k = 0; k < 64; k++) {
        ull xp = pack2(x2[k]);
        const ulonglong2* wr = (const ulonglong2*)(scr + 16384 + k*16);
        #pragma unroll
        for (int j = 0; j < 4; j++) {
            ulonglong2 w = wr[j];
            lg2[2*j+0] = ffma2(xp, w.x, lg2[2*j+0]);
            lg2[2*j+1] = ffma2(xp, w.y, lg2[2*j+1]);
        }
    }
    float lg[16];
    #pragma unroll
    for (int j = 0; j < 8; j++) {
        float2 v = unpack2(lg2[j]);
        lg[2*j] = v.x; lg[2*j+1] = v.y;
    }
    float mm = lg[0];
    #pragma unroll
    for (int j = 1; j < 16; j++) mm = fmaxf(mm, lg[j]);
    float ssum = 0.f;
    #pragma unroll
    for (int j = 0; j < 16; j++) ssum += __expf(lg[j] - mm);
    float lse = mm + logf(ssum);
    float4* op = (float4*)(out + ((size_t)blk*256 + t)*16);
    #pragma unroll
    for (int j4 = 0; j4 < 4; j4++)
        op[j4] = make_float4(lg[4*j4]-lse, lg[4*j4+1]-lse, lg[4*j4+2]-lse, lg[4*j4+3]-lse);
}

// ---------------- launch ----------------
extern "C" void kernel_launch(void* const* d_in, const int* in_sizes, int n_in,
                              void* d_out, int out_size) {
    const float* x    = (const float*)d_in[0];
    const int*   rows = (const int*)  d_in[1];
    const int*   cols = (const int*)  d_in[2];
    const float* vals = (const float*)d_in[3];
    const float* W1   = (const float*)d_in[4];
    const float* b1   = (const float*)d_in[5];
    const float* W2   = (const float*)d_in[6];
    const float* b2   = (const float*)d_in[7];
    const float* Wqkv = (const float*)d_in[8];
    const float* bqkv = (const float*)d_in[9];
    const float* Wo   = (const float*)d_in[10];
    const float* bo   = (const float*)d_in[11];
    const float* g1   = (const float*)d_in[12];
    const float* be1  = (const float*)d_in[13];
    const float* Wf1  = (const float*)d_in[14];
    const float* bf1  = (const float*)d_in[15];
    const float* Wf2  = (const float*)d_in[16];
    const float* bf2  = (const float*)d_in[17];
    const float* g2   = (const float*)d_in[18];
    const float* be2  = (const float*)d_in[19];
    const float* Wc   = (const float*)d_in[20];
    const float* bc   = (const float*)d_in[21];
    float* out = (float*)d_out;

    static bool attr_set = false;
    if (!attr_set) {
        cudaFuncSetAttribute(k_tr, cudaFuncAttributeMaxDynamicSharedMemorySize, SMEM_BYTES);
        attr_set = true;
    }

    k_csr    <<<GRID_P, 256>>>(rows, cols, vals);
    k_xw1    <<<NN/256, 256>>>(x, W1);
    k_spmm12 <<<GRID_P, 256>>>(b1, W2, b2);
    k_tr     <<<NN/256, 256, SMEM_BYTES>>>(Wqkv, bqkv, Wo, bo, g1, be1,
                                           Wf1, bf1, Wf2, bf2, g2, be2,
                                           Wc, bc, out);
}

// round 13
// speedup vs baseline: 1.1683x; 1.1683x over previous
#include <cuda_runtime.h>
#include <math.h>

#define NN      131072
#define DEG     16
#define NNZE    (NN*DEG)

typedef unsigned long long ull;

// ---- packed f32x2 helpers (Blackwell FFMA2; bit-identical fp32 math) ----
__device__ __forceinline__ ull ffma2(ull a, ull b, ull c) {
    ull d; asm("fma.rn.f32x2 %0, %1, %2, %3;" : "=l"(d) : "l"(a), "l"(b), "l"(c)); return d;
}
__device__ __forceinline__ ull fmul2(ull a, ull b) {
    ull d; asm("mul.rn.f32x2 %0, %1, %2;" : "=l"(d) : "l"(a), "l"(b)); return d;
}
__device__ __forceinline__ ull pack2(float x) {
    ull r; asm("mov.b64 %0, {%1, %1};" : "=l"(r) : "f"(x)); return r;
}
__device__ __forceinline__ float2 unpack2(ull a) {
    float lo, hi; asm("mov.b64 {%0, %1}, %2;" : "=f"(lo), "=f"(hi) : "l"(a));
    return make_float2(lo, hi);
}

// ---------------- scratch (static device globals; no allocation) ----------------
__device__ float  g_y [NN*32];
__device__ float  g_h1[NN*32];
__device__ float  g_h2[NN*64];
__device__ int    g_cnt[NN];
__device__ int    g_rowptr[NN+1];
__device__ int    g_cursor[NN];
__device__ int    g_psum[512];
__device__ float2 g_packed[NNZE];

// ---------------- CSR build ----------------
__global__ void k_zero_cnt() {
    int i = blockIdx.x*blockDim.x + threadIdx.x;
    if (i < NN) g_cnt[i] = 0;
}

__global__ void k_hist(const int* __restrict__ rows) {
    int e = blockIdx.x*blockDim.x + threadIdx.x;
    if (e < NNZE) atomicAdd(&g_cnt[rows[e]], 1);
}

// parallel 3-stage scan
__global__ void k_scan1() {
    __shared__ int ss[256];
    int t = threadIdx.x, b = blockIdx.x;
    ss[t] = g_cnt[b*256 + t];
    __syncthreads();
    for (int off = 128; off > 0; off >>= 1) {
        if (t < off) ss[t] += ss[t+off];
        __syncthreads();
    }
    if (t == 0) g_psum[b] = ss[0];
}

__global__ void k_scan2() {
    __shared__ int ss[512];
    int t = threadIdx.x;
    ss[t] = g_psum[t];
    __syncthreads();
    for (int off = 1; off < 512; off <<= 1) {
        int v = (t >= off) ? ss[t-off] : 0;
        __syncthreads();
        ss[t] += v;
        __syncthreads();
    }
    g_psum[t] = ss[t];               // inclusive sums
}

__global__ void k_scan3() {
    __shared__ int ss[256];
    int t = threadIdx.x, b = blockIdx.x;
    int c = g_cnt[b*256 + t];
    ss[t] = c;
    __syncthreads();
    for (int off = 1; off < 256; off <<= 1) {
        int v = (t >= off) ? ss[t-off] : 0;
        __syncthreads();
        ss[t] += v;
        __syncthreads();
    }
    int base = (b == 0) ? 0 : g_psum[b-1];
    int excl = base + ss[t] - c;
    g_rowptr[b*256 + t] = excl;
    g_cursor[b*256 + t] = excl;
    if (b == 511 && t == 255) g_rowptr[NN] = g_psum[511];
}

__global__ void k_scatter(const int* __restrict__ rows, const int* __restrict__ cols,
                          const float* __restrict__ vals) {
    int e = blockIdx.x*blockDim.x + threadIdx.x;
    if (e < NNZE) {
        int r = rows[e];
        int pos = atomicAdd(&g_cursor[r], 1);
        g_packed[pos] = make_float2(__int_as_float(cols[e]), vals[e]);
    }
}

// ---------------- y = x @ W1  (project 128->32 BEFORE SpMM; packed FMA) ----------
__global__ void __launch_bounds__(256) k_xw1(const float* __restrict__ x,
                                             const float* __restrict__ W1) {
    __shared__ float sW[128*32];
    int t = threadIdx.x;
    for (int i = t; i < 1024; i += 256) ((float4*)sW)[i] = ((const float4*)W1)[i];
    __syncthreads();
    int row = blockIdx.x*256 + t;
    const float4* xr = (const float4*)(x + (size_t)row*128);
    ull acc[16];
    #pragma unroll
    for (int j = 0; j < 16; j++) acc[j] = 0ull;
    #pragma unroll 4
    for (int k4 = 0; k4 < 32; k4++) {
        float4 xv = xr[k4];
        #pragma unroll
        for (int c = 0; c < 4; c++) {
            float xk = (c==0) ? xv.x : (c==1) ? xv.y : (c==2) ? xv.z : xv.w;
            ull xp = pack2(xk);
            const ulonglong2* wr = (const ulonglong2*)(sW + (k4*4+c)*32);
            #pragma unroll
            for (int j = 0; j < 8; j++) {
                ulonglong2 w = wr[j];
                acc[2*j+0] = ffma2(xp, w.x, acc[2*j+0]);
                acc[2*j+1] = ffma2(xp, w.y, acc[2*j+1]);
            }
        }
    }
    ulonglong2* yo = (ulonglong2*)(g_y + (size_t)row*32);
    #pragma unroll
    for (int j = 0; j < 8; j++) {
        ulonglong2 u; u.x = acc[2*j]; u.y = acc[2*j+1];
        yo[j] = u;
    }
}

// ---------------- SpMM 1: h1 = relu(spmm(y) + b1)  (warp/row, 2-way MLP) ---------
__global__ void __launch_bounds__(256) k_spmm1(const float* __restrict__ b1) {
    int w = (blockIdx.x*256 + threadIdx.x) >> 5;
    int lane = threadIdx.x & 31;
    int s = g_rowptr[w], e = g_rowptr[w+1];
    float acc0 = 0.f, acc1 = 0.f;
    int i = s;
    for (; i + 1 < e; i += 2) {
        float2 pa = g_packed[i];
        float2 pb = g_packed[i+1];
        acc0 += pa.y * g_y[__float_as_int(pa.x)*32 + lane];
        acc1 += pb.y * g_y[__float_as_int(pb.x)*32 + lane];
    }
    if (i < e) {
        float2 pa = g_packed[i];
        acc0 += pa.y * g_y[__float_as_int(pa.x)*32 + lane];
    }
    g_h1[w*32 + lane] = fmaxf(acc0 + acc1 + b1[lane], 0.f);
}

// ---------------- SpMM 2 fused with @W2: h2 = relu(spmm(h1)@W2 + b2) -------------
__global__ void __launch_bounds__(256) k_spmm2(const float* __restrict__ W2,
                                               const float* __restrict__ b2) {
    __shared__ float sW[32*64];
    __shared__ float sz[8][33];
    int t = threadIdx.x;
    for (int i = t; i < 512; i += 256) ((float4*)sW)[i] = ((const float4*)W2)[i];
    __syncthreads();
    int w = (blockIdx.x*256 + t) >> 5;
    int wl = t >> 5, lane = t & 31;
    int s = g_rowptr[w], e = g_rowptr[w+1];
    float acc0 = 0.f, acc1 = 0.f;
    int i = s;
    for (; i + 1 < e; i += 2) {
        float2 pa = g_packed[i];
        float2 pb = g_packed[i+1];
        acc0 += pa.y * g_h1[__float_as_int(pa.x)*32 + lane];
        acc1 += pb.y * g_h1[__float_as_int(pb.x)*32 + lane];
    }
    if (i < e) {
        float2 pa = g_packed[i];
        acc0 += pa.y * g_h1[__float_as_int(pa.x)*32 + lane];
    }
    sz[wl][lane] = acc0 + acc1;
    __syncwarp();
    float o0 = b2[lane], o1 = b2[lane+32];
    #pragma unroll
    for (int k = 0; k < 32; k++) {
        float zv = sz[wl][k];
        o0 += zv * sW[k*64 + lane];
        o1 += zv * sW[k*64 + lane + 32];
    }
    size_t off = (size_t)w * 64;
    g_h2[off + lane]      = fmaxf(o0, 0.f);
    g_h2[off + lane + 32] = fmaxf(o1, 0.f);
}

// ---------------- transformer: head-split attention, Cauchy-Schwarz softmax bound
// smem: scr (17408 fl; Wqkv -> Q/O rows -> Wf1|Wf2|Wc)
//       sK (256x68), sV (256x68); sK reused for Wo, then (with sV) FFN hidden rows
#define SCR_FLOATS  17408
#define QO_STRIDE   66
#define KV_STRIDE   68
#define SH_STRIDE   133
#define SMEM_FLOATS (SCR_FLOATS + 2*256*KV_STRIDE)
#define SMEM_BYTES  (SMEM_FLOATS*4)

__device__ __forceinline__ void gemm64p(const float* xin,
                                        const float* __restrict__ sw, int ws,
                                        int coff, ull (&acc)[16]) {
    #pragma unroll
    for (int k = 0; k < 64; k++) {
        ull xp = pack2(xin[k]);
        const ulonglong2* wr = (const ulonglong2*)(sw + k*ws + coff);
        #pragma unroll
        for (int j = 0; j < 8; j++) {
            ulonglong2 w = wr[j];
            acc[2*j+0] = ffma2(xp, w.x, acc[2*j+0]);
            acc[2*j+1] = ffma2(xp, w.y, acc[2*j+1]);
        }
    }
}

__device__ __forceinline__ void layernorm64(float (&v)[64], const float* __restrict__ g,
                                            const float* __restrict__ b) {
    float mu = 0.f;
    #pragma unroll
    for (int j = 0; j < 64; j++) mu += v[j];
    mu *= (1.f/64.f);
    float var = 0.f;
    #pragma unroll
    for (int j = 0; j < 64; j++) { float d = v[j]-mu; var += d*d; }
    var *= (1.f/64.f);
    float inv = rsqrtf(var + 1e-5f);
    #pragma unroll
    for (int j = 0; j < 64; j++) v[j] = (v[j]-mu)*inv*g[j] + b[j];
}

__global__ void __launch_bounds__(256) k_tr(
    const float* __restrict__ Wqkv, const float* __restrict__ bqkv,
    const float* __restrict__ Wo,   const float* __restrict__ bo,
    const float* __restrict__ g1,   const float* __restrict__ be1,
    const float* __restrict__ Wf1,  const float* __restrict__ bf1,
    const float* __restrict__ Wf2,  const float* __restrict__ bf2,
    const float* __restrict__ g2,   const float* __restrict__ be2,
    const float* __restrict__ Wc,   const float* __restrict__ bc,
    float* __restrict__ out)
{
    extern __shared__ float sm[];
    __shared__ float sred[32];                 // 8 warps x 4 heads: max ||k||^2
    float* scr = sm;                           // 17408 floats
    float* sK  = sm + SCR_FLOATS;              // 256 x 68
    float* sV  = sK + 256*KV_STRIDE;           // 256 x 68
    float* sH  = sK;                           // FFN hidden rows 256 x 133 (K/V dead)
    int t = threadIdx.x;
    int blk = blockIdx.x;
    const float4* xr4 = (const float4*)(g_h2 + ((size_t)blk*256 + t)*64);

    // ---- B1: stage W_qkv (64x192 = 12288 floats) into scr ----
    for (int i = t; i < 3072; i += 256) ((float4*)scr)[i] = ((const float4*)Wqkv)[i];
    __syncthreads();

    // ---- qkv projection (thread = token); q2 regs, K/V -> smem; K-norms on the fly
    ull q2[32];
    float kn[4];
    #pragma unroll
    for (int ch = 0; ch < 6; ch++) {
        ull acc[16];
        const ull* bp = (const ull*)(bqkv + ch*32);
        #pragma unroll
        for (int j = 0; j < 16; j++) acc[j] = bp[j];
        #pragma unroll
        for (int k4 = 0; k4 < 16; k4++) {
            float4 xv = xr4[k4];
            #pragma unroll
            for (int c = 0; c < 4; c++) {
                float xk = (c==0) ? xv.x : (c==1) ? xv.y : (c==2) ? xv.z : xv.w;
                ull xp = pack2(xk);
                const ulonglong2* wr = (const ulonglong2*)(scr + (k4*4+c)*192 + ch*32);
                #pragma unroll
                for (int j = 0; j < 8; j++) {
                    ulonglong2 w = wr[j];
                    acc[2*j+0] = ffma2(xp, w.x, acc[2*j+0]);
                    acc[2*j+1] = ffma2(xp, w.y, acc[2*j+1]);
                }
            }
        }
        if (ch < 2) {
            #pragma unroll
            for (int j = 0; j < 16; j++) q2[ch*16 + j] = acc[j];
        } else {
            if (ch < 4) {                      // K chunks: accumulate per-head ||k||^2
                float s0 = 0.f, s1 = 0.f;
                #pragma unroll
                for (int j = 0; j < 8; j++) {
                    float2 v = unpack2(acc[j]);
                    s0 += v.x*v.x + v.y*v.y;
                }
                #pragma unroll
                for (int j = 8; j < 16; j++) {
                    float2 v = unpack2(acc[j]);
                    s1 += v.x*v.x + v.y*v.y;
                }
                kn[(ch-2)*2 + 0] = s0;
                kn[(ch-2)*2 + 1] = s1;
            }
            float* dst = ((ch < 4) ? sK : sV) + t*KV_STRIDE + (ch & 1)*32;
            #pragma unroll
            for (int j = 0; j < 8; j++) {
                ulonglong2 u; u.x = acc[2*j]; u.y = acc[2*j+1];
                ((ulonglong2*)dst)[j] = u;
            }
        }
    }
    // warp-reduce K-norm maxima; lane 0 publishes per-warp maxima
    #pragma unroll
    for (int h = 0; h < 4; h++) {
        #pragma unroll
        for (int off = 16; off > 0; off >>= 1)
            kn[h] = fmaxf(kn[h], __shfl_xor_sync(0xffffffffu, kn[h], off));
    }
    if ((t & 31) == 0) {
        #pragma unroll
        for (int h = 0; h < 4; h++) sred[(t >> 5)*4 + h] = kn[h];
    }
    __syncthreads();   // B2: Wqkv reads done; K/V complete; sred visible

    // ---- park q rows in scr (overwrites Wqkv) ----
    #pragma unroll
    for (int j = 0; j < 32; j++)
        *(ull*)&scr[t*QO_STRIDE + 2*j] = q2[j];
    __syncthreads();   // B2b: Q visible

    // ---- attention: thread = (head h, 4 tokens); single pass, CS bound shift ----
    {
        int h  = t >> 6;          // 0..3
        int tb = t & 63;          // token base
        float kmax2 = sred[h];
        #pragma unroll
        for (int w = 1; w < 8; w++) kmax2 = fmaxf(kmax2, sred[w*4 + h]);

        ull q[32];                // q[m*8+j] : token m, dim pair j (within head)
        float mx[4];              // shift: sqrt(||q||^2 * max||k||^2) >= any score
        #pragma unroll
        for (int m = 0; m < 4; m++) {
            int tok = tb + 64*m;
            float qs = 0.f;
            #pragma unroll
            for (int j = 0; j < 8; j++) {
                ull qq = *(const ull*)&scr[tok*QO_STRIDE + h*16 + 2*j];
                q[m*8+j] = qq;
                float2 v = unpack2(qq);
                qs += v.x*v.x + v.y*v.y;
            }
            mx[m] = sqrtf(qs * kmax2);
        }

        float l[4];
        ull c[32];
        #pragma unroll
        for (int m = 0; m < 4; m++) l[m] = 0.f;
        #pragma unroll
        for (int j = 0; j < 32; j++) c[j] = 0ull;
        for (int kk = 0; kk < 256; kk++) {
            const ulonglong2* kp = (const ulonglong2*)(sK + kk*KV_STRIDE + h*16);
            ulonglong2 kA = kp[0], kB = kp[1], kC = kp[2], kD = kp[3];
            const ulonglong2* vp = (const ulonglong2*)(sV + kk*KV_STRIDE + h*16);
            ulonglong2 vA = vp[0], vB = vp[1], vC = vp[2], vD = vp[3];
            #pragma unroll
            for (int m = 0; m < 4; m++) {
                ull sa = fmul2(q[m*8+0], kA.x);
                ull sb = fmul2(q[m*8+1], kA.y);
                sa = ffma2(q[m*8+2], kB.x, sa);
                sb = ffma2(q[m*8+3], kB.y, sb);
                sa = ffma2(q[m*8+4], kC.x, sa);
                sb = ffma2(q[m*8+5], kC.y, sb);
                sa = ffma2(q[m*8+6], kD.x, sa);
                sb = ffma2(q[m*8+7], kD.y, sb);
                float2 u = unpack2(sa), v = unpack2(sb);
                float p = __expf((((u.x+u.y)+(v.x+v.y)) - mx[m]) * 0.25f);
                l[m] += p;
                ull pp = pack2(p);
                c[m*8+0] = ffma2(pp, vA.x, c[m*8+0]);
                c[m*8+1] = ffma2(pp, vA.y, c[m*8+1]);
                c[m*8+2] = ffma2(pp, vB.x, c[m*8+2]);
                c[m*8+3] = ffma2(pp, vB.y, c[m*8+3]);
                c[m*8+4] = ffma2(pp, vC.x, c[m*8+4]);
                c[m*8+5] = ffma2(pp, vC.y, c[m*8+5]);
                c[m*8+6] = ffma2(pp, vD.x, c[m*8+6]);
                c[m*8+7] = ffma2(pp, vD.y, c[m*8+7]);
            }
        }

        // normalize + write o to scr (same cells this thread read q from: no race)
        #pragma unroll
        for (int m = 0; m < 4; m++) {
            int tok = tb + 64*m;
            ull inv = pack2(1.f / l[m]);
            #pragma unroll
            for (int j = 0; j < 8; j++)
                *(ull*)&scr[tok*QO_STRIDE + h*16 + 2*j] = fmul2(c[m*8+j], inv);
        }
    }
    __syncthreads();   // B3: attention done, O complete, K/V dead

    // stage W_o (64x64 = 4096 floats) into sK
    for (int i = t; i < 1024; i += 256) ((float4*)sK)[i] = ((const float4*)Wo)[i];
    __syncthreads();   // B4

    // ---- a = o @ W_o + b_o;  x1 = LN1(x + a)  (thread = token) ----
    float o[64];
    #pragma unroll
    for (int j = 0; j < 32; j++) {
        float2 v = unpack2(*(const ull*)&scr[t*QO_STRIDE + 2*j]);
        o[2*j] = v.x; o[2*j+1] = v.y;
    }
    float x1[64];
    #pragma unroll
    for (int ch = 0; ch < 2; ch++) {
        ull acc[16];
        const ull* bp = (const ull*)(bo + ch*32);
        #pragma unroll
        for (int j = 0; j < 16; j++) acc[j] = bp[j];
        gemm64p(o, sK, 64, ch*32, acc);
        #pragma unroll
        for (int j = 0; j < 16; j++) {
            float2 v = unpack2(acc[j]);
            x1[ch*32 + 2*j + 0] = v.x;
            x1[ch*32 + 2*j + 1] = v.y;
        }
    }
    #pragma unroll
    for (int k4 = 0; k4 < 16; k4++) {
        float4 xv = xr4[k4];
        x1[4*k4+0] += xv.x; x1[4*k4+1] += xv.y; x1[4*k4+2] += xv.z; x1[4*k4+3] += xv.w;
    }
    layernorm64(x1, g1, be1);
    __syncthreads();   // B5: O and W_o dead

    // stage Wf1 (8192), Wf2 (8192), Wc (1024) into scr
    for (int i = t; i < 2048; i += 256) ((float4*)scr)[i] = ((const float4*)Wf1)[i];
    for (int i = t; i < 2048; i += 256) ((float4*)(scr + 8192))[i] = ((const float4*)Wf2)[i];
    for (int i = t; i < 256;  i += 256) ((float4*)(scr + 16384))[i] = ((const float4*)Wc)[i];
    __syncthreads();   // B5b

    // ---- FFN up: h = gelu(x1 @ W_ff1 + b_ff1) -> own smem row (no sync needed) --
    float* hrow = sH + t*SH_STRIDE;
    #pragma unroll
    for (int ch = 0; ch < 4; ch++) {
        ull acc[16];
        const ull* bp = (const ull*)(bf1 + ch*32);
        #pragma unroll
        for (int j = 0; j < 16; j++) acc[j] = bp[j];
        gemm64p(x1, scr, 128, ch*32, acc);
        #pragma unroll
        for (int j = 0; j < 16; j++) {
            float2 v = unpack2(acc[j]);
            hrow[ch*32 + 2*j + 0] = 0.5f*v.x*(1.f + erff(v.x*0.70710678118654752f));
            hrow[ch*32 + 2*j + 1] = 0.5f*v.y*(1.f + erff(v.y*0.70710678118654752f));
        }
    }

    // ---- FFN down + residual + LN2 ----
    float x2[64];
    #pragma unroll
    for (int ch = 0; ch < 2; ch++) {
        ull acc[16];
        const ull* bp = (const ull*)(bf2 + ch*32);
        #pragma unroll
        for (int j = 0; j < 16; j++) acc[j] = bp[j];
        #pragma unroll 4
        for (int k = 0; k < 128; k++) {
            ull hp = pack2(hrow[k]);
            const ulonglong2* wr = (const ulonglong2*)(scr + 8192 + k*64 + ch*32);
            #pragma unroll
            for (int j = 0; j < 8; j++) {
                ulonglong2 w = wr[j];
                acc[2*j+0] = ffma2(hp, w.x, acc[2*j+0]);
                acc[2*j+1] = ffma2(hp, w.y, acc[2*j+1]);
            }
        }
        #pragma unroll
        for (int j = 0; j < 16; j++) {
            float2 v = unpack2(acc[j]);
            x2[ch*32 + 2*j + 0] = v.x + x1[ch*32 + 2*j + 0];
            x2[ch*32 + 2*j + 1] = v.y + x1[ch*32 + 2*j + 1];
        }
    }
    layernorm64(x2, g2, be2);

    // ---- classifier + log_softmax ----
    ull lg2[8];
    const ull* bcp = (const ull*)bc;
    #pragma unroll
    for (int j = 0; j < 8; j++) lg2[j] = bcp[j];
    #pragma unroll
    for (int k = 0; k < 64; k++) {
        ull xp = pack2(x2[k]);
        const ulonglong2* wr = (const ulonglong2*)(scr + 16384 + k*16);
        #pragma unroll
        for (int j = 0; j < 4; j++) {
            ulonglong2 w = wr[j];
            lg2[2*j+0] = ffma2(xp, w.x, lg2[2*j+0]);
            lg2[2*j+1] = ffma2(xp, w.y, lg2[2*j+1]);
        }
    }
    float lg[16];
    #pragma unroll
    for (int j = 0; j < 8; j++) {
        float2 v = unpack2(lg2[j]);
        lg[2*j] = v.x; lg[2*j+1] = v.y;
    }
    float mm = lg[0];
    #pragma unroll
    for (int j = 1; j < 16; j++) mm = fmaxf(mm, lg[j]);
    float ssum = 0.f;
    #pragma unroll
    for (int j = 0; j < 16; j++) ssum += __expf(lg[j] - mm);
    float lse = mm + logf(ssum);
    float4* op = (float4*)(out + ((size_t)blk*256 + t)*16);
    #pragma unroll
    for (int j4 = 0; j4 < 4; j4++)
        op[j4] = make_float4(lg[4*j4]-lse, lg[4*j4+1]-lse, lg[4*j4+2]-lse, lg[4*j4+3]-lse);
}

// ---------------- launch ----------------
extern "C" void kernel_launch(void* const* d_in, const int* in_sizes, int n_in,
                              void* d_out, int out_size) {
    const float* x    = (const float*)d_in[0];
    const int*   rows = (const int*)  d_in[1];
    const int*   cols = (const int*)  d_in[2];
    const float* vals = (const float*)d_in[3];
    const float* W1   = (const float*)d_in[4];
    const float* b1   = (const float*)d_in[5];
    const float* W2   = (const float*)d_in[6];
    const float* b2   = (const float*)d_in[7];
    const float* Wqkv = (const float*)d_in[8];
    const float* bqkv = (const float*)d_in[9];
    const float* Wo   = (const float*)d_in[10];
    const float* bo   = (const float*)d_in[11];
    const float* g1   = (const float*)d_in[12];
    const float* be1  = (const float*)d_in[13];
    const float* Wf1  = (const float*)d_in[14];
    const float* bf1  = (const float*)d_in[15];
    const float* Wf2  = (const float*)d_in[16];
    const float* bf2  = (const float*)d_in[17];
    const float* g2   = (const float*)d_in[18];
    const float* be2  = (const float*)d_in[19];
    const float* Wc   = (const float*)d_in[20];
    const float* bc   = (const float*)d_in[21];
    float* out = (float*)d_out;

    static bool attr_set = false;
    if (!attr_set) {
        cudaFuncSetAttribute(k_tr, cudaFuncAttributeMaxDynamicSharedMemorySize, SMEM_BYTES);
        attr_set = true;
    }

    k_zero_cnt<<<NN/256, 256>>>();
    k_hist    <<<NNZE/256, 256>>>(rows);
    k_scan1   <<<512, 256>>>();
    k_scan2   <<<1, 512>>>();
    k_scan3   <<<512, 256>>>();
    k_scatter <<<NNZE/256, 256>>>(rows, cols, vals);
    k_xw1     <<<NN/256, 256>>>(x, W1);
    k_spmm1   <<<NN/8, 256>>>(b1);
    k_spmm2   <<<NN/8, 256>>>(W2, b2);
    k_tr      <<<NN/256, 256, SMEM_BYTES>>>(Wqkv, bqkv, Wo, bo, g1, be1,
                                            Wf1, bf1, Wf2, bf2, g2, be2,
                                            Wc, bc, out);
}